// round 9
// baseline (speedup 1.0000x reference)
#include <cuda_runtime.h>
#include <cuda_bf16.h>

// EMA scan y[n] = w*x[n] + (1-w)*y[n-1] over the contiguous frames axis (2048).
// input (16,8,256,2048) f32; initial_state (16,8,256); weight (8,256) clamped.
//
// R8: single-wave persistent warps. grid = 1024 CTAs (all resident at once,
// zero wave transitions); each warp owns 8 channels at stride 4096 (so the
// weight -- index (g + c*4096) & 2047 = g & 2047 -- and all decay powers are
// per-warp invariant). The 8-deep register ring refills ACROSS channel
// boundaries, so the warp's read stream never drains: while scanning/storing
// channel c it is already loading channel c+1's first 8 float4s.
//
// Per 4-frame segment the recurrence is the affine map y -> r*y + b with the
// same r = (1-w)^4 across lanes; only the offset b is Kogge-Stone scanned
// (5 shuffles, multipliers r^d). Carry chains across rounds and channels.

#define NFRAMES     2048
#define NCHANNELS   (16 * 8 * 256)      // 32768
#define WARPS_PER_CTA 4
#define NROUNDS     16
#define RING        8
#define CH_PER_WARP 8
#define TOTAL_WARPS (NCHANNELS / CH_PER_WARP)     // 4096
#define NCTAS       (TOTAL_WARPS / WARPS_PER_CTA) // 1024
#define CH_STRIDE   TOTAL_WARPS                   // 4096 channels

__device__ __forceinline__ float4 ldcs4(const float4* p) {
    float4 v;
    asm volatile("ld.global.cs.L2::256B.v4.f32 {%0,%1,%2,%3}, [%4];"
                 : "=f"(v.x), "=f"(v.y), "=f"(v.z), "=f"(v.w) : "l"(p));
    return v;
}
__device__ __forceinline__ void stcs4(float4* p, float4 v) {
    asm volatile("st.global.cs.v4.f32 [%0], {%1,%2,%3,%4};"
                 :: "l"(p), "f"(v.x), "f"(v.y), "f"(v.z), "f"(v.w) : "memory");
}

__global__ __launch_bounds__(32 * WARPS_PER_CTA, 8)
void ema_scan_kernel(const float* __restrict__ in,
                     const float* __restrict__ init_state,
                     const float* __restrict__ wt,
                     float* __restrict__ out)
{
    const int lane = threadIdx.x & 31;
    const int warp = threadIdx.x >> 5;
    const int g    = blockIdx.x * WARPS_PER_CTA + warp;   // global warp id

    // Weight is invariant across this warp's 8 channels (stride 4096 ≡ 0 mod 2048)
    float w = wt[g & 2047];
    w = fminf(fmaxf(w, 0.0f), 1.0f);
    const float omw = 1.0f - w;

    // Powers of r = (1-w)^4
    float r1 = omw * omw; r1 = r1 * r1;
    const float r2  = r1 * r1;
    const float r4  = r2 * r2;
    const float r8  = r4 * r4;
    const float r16 = r8 * r8;

    // r^(lane+1) for the exit-state FMA
    float rl = r1;
    if (lane & 1)  rl *= r1;
    if (lane & 2)  rl *= r2;
    if (lane & 4)  rl *= r4;
    if (lane & 8)  rl *= r8;
    if (lane & 16) rl *= r16;
    const float rlr = rl;

    const size_t CH_F4 = (size_t)CH_STRIDE * (NFRAMES / 4);  // float4 stride between channels

    const float4* ip_cur = reinterpret_cast<const float4*>(in + (size_t)g * NFRAMES);

    // Prime the ring with channel 0, rounds 0..7
    float4 xs[RING];
    #pragma unroll
    for (int k = 0; k < RING; ++k)
        xs[k] = ldcs4(ip_cur + k * 32 + lane);

    float yinit_cur = init_state[g];

    for (int c = 0; c < CH_PER_WARP; ++c) {
        const float4* ip_next = ip_cur + CH_F4;

        // Prefetch next channel's initial state (latency hidden by inner loop)
        float yinit_next = 0.0f;
        if (c + 1 < CH_PER_WARP)
            yinit_next = __ldg(init_state + g + (c + 1) * CH_STRIDE);

        float4* op = reinterpret_cast<float4*>(out + (size_t)(g + c * CH_STRIDE) * NFRAMES);
        float ycarry = yinit_cur;

        #pragma unroll
        for (int k = 0; k < NROUNDS; ++k) {
            const float4 x = xs[k % RING];

            // Refill: rounds k+8 of this channel, then rounds 0..7 of the next
            if (k < RING) {
                xs[k % RING] = ldcs4(ip_cur + (k + RING) * 32 + lane);
            } else if (c + 1 < CH_PER_WARP) {
                xs[k % RING] = ldcs4(ip_next + (k - RING) * 32 + lane);
            }

            // Segment offset: 4-frame local recurrence from zero state
            float b = w * x.x;
            b = omw * b + w * x.y;
            b = omw * b + w * x.z;
            b = omw * b + w * x.w;

            // Inclusive Kogge-Stone scan of b; active lanes' multiplier is r^d
            float p;
            p = __shfl_up_sync(0xffffffffu, b, 1);  if (lane >= 1)  b = r1  * p + b;
            p = __shfl_up_sync(0xffffffffu, b, 2);  if (lane >= 2)  b = r2  * p + b;
            p = __shfl_up_sync(0xffffffffu, b, 4);  if (lane >= 4)  b = r4  * p + b;
            p = __shfl_up_sync(0xffffffffu, b, 8);  if (lane >= 8)  b = r8  * p + b;
            p = __shfl_up_sync(0xffffffffu, b, 16); if (lane >= 16) b = r16 * p + b;

            // Exit state of this lane's segment; entering state; round carry
            const float yexit  = rlr * ycarry + b;
            float yenter = __shfl_up_sync(0xffffffffu, yexit, 1);
            if (lane == 0) yenter = ycarry;
            ycarry = __shfl_sync(0xffffffffu, yexit, 31);

            // Replay exactly as the reference recurrence
            float y = yenter;
            float4 o;
            y = w * x.x + omw * y; o.x = y;
            y = w * x.y + omw * y; o.y = y;
            y = w * x.z + omw * y; o.z = y;
            y = w * x.w + omw * y; o.w = y;

            stcs4(op + k * 32 + lane, o);
        }

        ip_cur    = ip_next;
        yinit_cur = yinit_next;
    }
}

extern "C" void kernel_launch(void* const* d_in, const int* in_sizes, int n_in,
                              void* d_out, int out_size)
{
    const float* input   = (const float*)d_in[0];
    const float* init_st = (const float*)d_in[1];
    const float* weight  = (const float*)d_in[2];
    float* out = (float*)d_out;

    ema_scan_kernel<<<NCTAS, 32 * WARPS_PER_CTA>>>(input, init_st, weight, out);
}

// round 12
// speedup vs baseline: 1.1553x; 1.1553x over previous
#include <cuda_runtime.h>
#include <cuda_bf16.h>

// EMA scan y[n] = w*x[n] + (1-w)*y[n-1] over the contiguous frames axis (2048).
// input (16,8,256,2048) f32; initial_state (16,8,256); weight (8,256) clamped.
//
// Best-known structure (R7): warp-autonomous, one warp per channel, 16 rounds
// of 128 frames, lane l owns float4 32k+l -> perfectly coalesced LDG/STG.128.
// Per 4-frame segment the recurrence is the affine map y -> r*y + b with the
// same r = (1-w)^4 across lanes, so only the offset b is Kogge-Stone scanned
// (5 shuffles, multipliers r^d). 8-deep register ring sustains MLP.
//
// R9/R10: 8 warps per CTA (256 threads, grid 4096) — halves per-CTA
// launch/drain bookkeeping at identical occupancy. (R10 rerun: previous
// submission hit a container infra failure, no measurement was taken.)

#define NFRAMES   2048
#define NCHANNELS (16 * 8 * 256)
#define WARPS_PER_CTA 8
#define NROUNDS   16
#define RING      8

__device__ __forceinline__ float4 ldcs4(const float4* p) {
    float4 v;
    asm volatile("ld.global.cs.L2::256B.v4.f32 {%0,%1,%2,%3}, [%4];"
                 : "=f"(v.x), "=f"(v.y), "=f"(v.z), "=f"(v.w) : "l"(p));
    return v;
}
__device__ __forceinline__ void stcs4(float4* p, float4 v) {
    asm volatile("st.global.cs.v4.f32 [%0], {%1,%2,%3,%4};"
                 :: "l"(p), "f"(v.x), "f"(v.y), "f"(v.z), "f"(v.w) : "memory");
}

__global__ __launch_bounds__(32 * WARPS_PER_CTA, 4)
void ema_scan_kernel(const float* __restrict__ in,
                     const float* __restrict__ init_state,
                     const float* __restrict__ wt,
                     float* __restrict__ out)
{
    const int lane = threadIdx.x & 31;
    const int warp = threadIdx.x >> 5;
    const int ch   = blockIdx.x * WARPS_PER_CTA + warp;

    float w = wt[ch & 2047];
    w = fminf(fmaxf(w, 0.0f), 1.0f);
    const float omw = 1.0f - w;

    const float4* ip = reinterpret_cast<const float4*>(in + (size_t)ch * NFRAMES);
    float4*       op = reinterpret_cast<float4*>(out + (size_t)ch * NFRAMES);

    // Prime the ring: first 8 rounds' data in flight
    float4 xs[RING];
    #pragma unroll
    for (int k = 0; k < RING; ++k)
        xs[k] = ldcs4(ip + k * 32 + lane);

    // Powers of r = (1-w)^4
    float r1 = omw * omw; r1 = r1 * r1;
    const float r2  = r1 * r1;
    const float r4  = r2 * r2;
    const float r8  = r4 * r4;
    const float r16 = r8 * r8;

    // r^(lane+1) for the exit-state FMA
    float rl = r1;
    if (lane & 1)  rl *= r1;
    if (lane & 2)  rl *= r2;
    if (lane & 4)  rl *= r4;
    if (lane & 8)  rl *= r8;
    if (lane & 16) rl *= r16;
    const float rlr = rl;

    float ycarry = init_state[ch];

    #pragma unroll
    for (int k = 0; k < NROUNDS; ++k) {
        const float4 x = xs[k % RING];
        // Refill this slot with round k+8 (keeps ~8 loads in flight)
        if (k + RING < NROUNDS)
            xs[k % RING] = ldcs4(ip + (k + RING) * 32 + lane);

        // Segment offset: 4-frame local recurrence from zero state
        float b = w * x.x;
        b = omw * b + w * x.y;
        b = omw * b + w * x.z;
        b = omw * b + w * x.w;

        // Inclusive Kogge-Stone scan of b; active lanes' multiplier is r^d
        float p;
        p = __shfl_up_sync(0xffffffffu, b, 1);  if (lane >= 1)  b = r1  * p + b;
        p = __shfl_up_sync(0xffffffffu, b, 2);  if (lane >= 2)  b = r2  * p + b;
        p = __shfl_up_sync(0xffffffffu, b, 4);  if (lane >= 4)  b = r4  * p + b;
        p = __shfl_up_sync(0xffffffffu, b, 8);  if (lane >= 8)  b = r8  * p + b;
        p = __shfl_up_sync(0xffffffffu, b, 16); if (lane >= 16) b = r16 * p + b;

        // Exit state of this lane's segment; entering state; round carry
        const float yexit  = rlr * ycarry + b;
        float yenter = __shfl_up_sync(0xffffffffu, yexit, 1);
        if (lane == 0) yenter = ycarry;
        ycarry = __shfl_sync(0xffffffffu, yexit, 31);

        // Replay exactly as the reference recurrence
        float y = yenter;
        float4 o;
        y = w * x.x + omw * y; o.x = y;
        y = w * x.y + omw * y; o.y = y;
        y = w * x.z + omw * y; o.z = y;
        y = w * x.w + omw * y; o.w = y;

        stcs4(op + k * 32 + lane, o);
    }
}

extern "C" void kernel_launch(void* const* d_in, const int* in_sizes, int n_in,
                              void* d_out, int out_size)
{
    const float* input   = (const float*)d_in[0];
    const float* init_st = (const float*)d_in[1];
    const float* weight  = (const float*)d_in[2];
    float* out = (float*)d_out;

    ema_scan_kernel<<<NCHANNELS / WARPS_PER_CTA, 32 * WARPS_PER_CTA>>>(
        input, init_st, weight, out);
}